// round 15
// baseline (speedup 1.0000x reference)
#include <cuda_runtime.h>
#include <cuda_fp16.h>
#include <math.h>
#include <cstdint>

#define BB 4
#define TT 1024
#define DD 1024
#define HH 16
#define HSS 64

// Scratch (no cudaMalloc allowed)
__device__ __align__(16) __half g_xh[BB*TT*DD];            // x in fp16
__device__ __align__(16) unsigned g_wp[3*HH*512*HSS];      // W q/k/v paired: [which][h][kp][hs]
__device__ __align__(16) unsigned g_wop[512*DD];           // Wo paired: [kp][n]
__device__ __align__(16) __half g_q[BB*HH*TT*HSS];
__device__ __align__(16) __half g_k[BB*HH*TT*HSS];
__device__ __align__(16) __half g_v[BB*HH*TT*HSS];
__device__ __align__(16) __half g_att[BB*TT*DD];

// ---------------------------------------------------------------------------
// helpers
// ---------------------------------------------------------------------------
__device__ __forceinline__ void mma16h(float* d, const unsigned* a, const unsigned* b) {
    asm volatile(
        "mma.sync.aligned.m16n8k16.row.col.f32.f16.f16.f32 "
        "{%0,%1,%2,%3}, {%4,%5,%6,%7}, {%8,%9}, {%0,%1,%2,%3};"
        : "+f"(d[0]), "+f"(d[1]), "+f"(d[2]), "+f"(d[3])
        : "r"(a[0]), "r"(a[1]), "r"(a[2]), "r"(a[3]),
          "r"(b[0]), "r"(b[1]));
}

__device__ __forceinline__ void ldsm4(unsigned& r0, unsigned& r1,
                                      unsigned& r2, unsigned& r3, uint32_t addr) {
    asm volatile("ldmatrix.sync.aligned.m8n8.x4.shared.b16 {%0,%1,%2,%3}, [%4];"
                 : "=r"(r0), "=r"(r1), "=r"(r2), "=r"(r3) : "r"(addr));
}

__device__ __forceinline__ unsigned packh2(float a, float b) {
    __half2 h = __floats2half2_rn(a, b);
    return *reinterpret_cast<unsigned*>(&h);
}

__device__ __forceinline__ uint32_t smem_u32(const void* p) {
    uint32_t a;
    asm("{ .reg .u64 t; cvta.to.shared.u64 t, %1; cvt.u32.u64 %0, t; }"
        : "=r"(a) : "l"(p));
    return a;
}

__device__ __forceinline__ void cp16(uint32_t s, const void* g) {
    asm volatile("cp.async.cg.shared.global [%0], [%1], 16;"
                 :: "r"(s), "l"(g) : "memory");
}
#define CP_COMMIT() asm volatile("cp.async.commit_group;" ::: "memory")
#define CP_WAIT1()  asm volatile("cp.async.wait_group 1;" ::: "memory")
#define CP_WAIT0()  asm volatile("cp.async.wait_group 0;" ::: "memory")

// ---------------------------------------------------------------------------
// Convert/pack kernels. conv_main: x + Wq/Wk/Wv (needed by qkv).
// conv_wo: Wo pack (needed only by proj; forked to overlap qkv/attn).
// ---------------------------------------------------------------------------
__global__ void conv_main(const float* __restrict__ x,
                          const float* __restrict__ Wq,
                          const float* __restrict__ Wk,
                          const float* __restrict__ Wv)
{
    const int stride = gridDim.x * blockDim.x;
    const int tid0 = blockIdx.x * blockDim.x + threadIdx.x;

    const int XN8 = (BB * TT * DD) / 8;        // 524288
    for (int i = tid0; i < XN8; i += stride) {
        float4 v0 = reinterpret_cast<const float4*>(x)[2 * i];
        float4 v1 = reinterpret_cast<const float4*>(x)[2 * i + 1];
        uint4 o;
        o.x = packh2(v0.x, v0.y);
        o.y = packh2(v0.z, v0.w);
        o.z = packh2(v1.x, v1.y);
        o.w = packh2(v1.z, v1.w);
        reinterpret_cast<uint4*>(g_xh)[i] = o;
    }

    const int WP4 = (3 * HH * 512 * HSS) / 4;  // 393216
    for (int i = tid0; i < WP4; i += stride) {
        int w0 = i * 4;
        int hs = w0 & 63;
        int kp = (w0 >> 6) & 511;
        int h  = (w0 >> 15) & 15;
        int which = w0 >> 19;
        const float* W = (which == 0 ? Wq : which == 1 ? Wk : Wv);
        const float* s0 = W + ((size_t)h * DD + 2 * kp) * HSS + hs;
        float4 a = *reinterpret_cast<const float4*>(s0);
        float4 b = *reinterpret_cast<const float4*>(s0 + HSS);
        uint4 o;
        o.x = packh2(a.x, b.x); o.y = packh2(a.y, b.y);
        o.z = packh2(a.z, b.z); o.w = packh2(a.w, b.w);
        reinterpret_cast<uint4*>(g_wp)[i] = o;
    }
}

__global__ void conv_wo(const float* __restrict__ Wo)
{
    const int stride = gridDim.x * blockDim.x;
    const int tid0 = blockIdx.x * blockDim.x + threadIdx.x;
    const int WO4 = (512 * DD) / 4;            // 131072
    for (int i = tid0; i < WO4; i += stride) {
        int w0 = i * 4;
        int n  = w0 & 1023;
        int kp = w0 >> 10;
        const float* s0 = Wo + (size_t)(2 * kp) * DD + n;
        float4 a = *reinterpret_cast<const float4*>(s0);
        float4 b = *reinterpret_cast<const float4*>(s0 + DD);
        uint4 o;
        o.x = packh2(a.x, b.x); o.y = packh2(a.y, b.y);
        o.z = packh2(a.z, b.z); o.w = packh2(a.w, b.w);
        reinterpret_cast<uint4*>(g_wop)[i] = o;
    }
}

// ---------------------------------------------------------------------------
// fp16 GEMM: block 128x128, 8 warps = 2(m) x 4(n), warp 64x32, BK=64.
// Aw[row 128][kp 32 + pad4]  -> ldmatrix.x4 for A fragments
// Bw[kp 32][n 128 + pad8]    -> scalar frags (packed k-pairs)
// 3-stage cp.async pipeline, 16 k-chunks.
// ---------------------------------------------------------------------------
#define AW_STRIDE 36
#define BW_STRIDE 136
#define AW_WORDS  (128 * AW_STRIDE)     // 4608
#define BW_WORDS  (32 * BW_STRIDE)      // 4352
#define NSTAGE 3
#define NCHUNK 16
#define PIPE_SMEM ((AW_WORDS + BW_WORDS) * NSTAGE * 4)   // 107520 bytes

__device__ __forceinline__ uint32_t a_lane_off(int lane) {
    int r = (lane & 7) + ((lane >> 3) & 1) * 8;
    int c = (lane & 16) ? 4 : 0;
    return (uint32_t)(r * AW_STRIDE + c) * 4;
}

__device__ __forceinline__ void gemm_mma_chunk(
    uint32_t aw_addr0, const unsigned* __restrict__ Bw,
    float acc[4][4][4], int wn, int lq, int lr)
{
#pragma unroll
    for (int kc = 0; kc < 4; kc++) {
        const int kb = kc * 8 + lr;
        unsigned a[4][4];
#pragma unroll
        for (int mf = 0; mf < 4; mf++)
            ldsm4(a[mf][0], a[mf][1], a[mf][2], a[mf][3],
                  aw_addr0 + (uint32_t)(mf * 16 * AW_STRIDE + kc * 8) * 4);
        unsigned b[4][2];
#pragma unroll
        for (int nf = 0; nf < 4; nf++) {
            int nc = wn * 32 + nf * 8 + lq;
            b[nf][0] = Bw[kb * BW_STRIDE + nc];
            b[nf][1] = Bw[(kb + 4) * BW_STRIDE + nc];
        }
#pragma unroll
        for (int mf = 0; mf < 4; mf++)
#pragma unroll
            for (int nf = 0; nf < 4; nf++)
                mma16h(acc[mf][nf], a[mf], b[nf]);
    }
}

// ---------------------------------------------------------------------------
// QKV: logical GEMM [4096 x 3072 x 1024]. grid (24, 32): x = nt (fast), y = mt.
// ---------------------------------------------------------------------------
__device__ __forceinline__ void qkv_issue(
    uint32_t a_s, uint32_t b_s, int mt, const unsigned* Wp, int h0, int k0, int tid)
{
#pragma unroll
    for (int i = 0; i < 4; i++) {
        int u = tid + i * 256;
        int row = u >> 3;
        int q4  = u & 7;
        cp16(a_s + (row * AW_STRIDE + q4 * 4) * 4,
             &g_xh[(size_t)(mt * 128 + row) * DD + k0 + q4 * 8]);
    }
#pragma unroll
    for (int i = 0; i < 4; i++) {
        int u = tid + i * 256;
        int kp = u >> 5;
        int n  = (u & 31) * 4;
        int h  = h0 + (n >> 6);
        int hs = n & 63;
        cp16(b_s + (kp * BW_STRIDE + n) * 4,
             &Wp[((size_t)h * 512 + (k0 >> 1) + kp) * HSS + hs]);
    }
}

__global__ __launch_bounds__(256, 2) void qkv_kernel()
{
    extern __shared__ unsigned dsm[];
    unsigned* AwB = dsm;
    unsigned* BwB = dsm + NSTAGE * AW_WORDS;
    const uint32_t a_base = smem_u32(AwB);
    const uint32_t b_base = smem_u32(BwB);

    const int nt = blockIdx.x;           // 0..23
    const int mt = blockIdx.y;           // 0..31
    const int which = nt >> 3;
    const int h0 = (nt & 7) * 2;

    __half* dst = (which == 0 ? g_q : which == 1 ? g_k : g_v);
    const unsigned* Wp = g_wp + (size_t)which * HH * 512 * HSS;

    const int tid  = threadIdx.x;
    const int lane = tid & 31;
    const int warp = tid >> 5;
    const int wm   = warp >> 2;
    const int wn   = warp & 3;
    const int lq   = lane >> 2;
    const int lr   = lane & 3;
    const uint32_t aoff = (uint32_t)(wm * 64 * AW_STRIDE) * 4 + a_lane_off(lane);

    float acc[4][4][4];
#pragma unroll
    for (int mf = 0; mf < 4; mf++)
#pragma unroll
        for (int nf = 0; nf < 4; nf++)
#pragma unroll
            for (int j = 0; j < 4; j++) acc[mf][nf][j] = 0.f;

    qkv_issue(a_base, b_base, mt, Wp, h0, 0, tid);
    CP_COMMIT();
    qkv_issue(a_base + AW_WORDS * 4, b_base + BW_WORDS * 4, mt, Wp, h0, 64, tid);
    CP_COMMIT();

    for (int ci = 0; ci < NCHUNK; ci++) {
        if (ci < NCHUNK - 2) CP_WAIT1(); else CP_WAIT0();
        __syncthreads();
        if (ci + 2 < NCHUNK) {
            int s = (ci + 2) % NSTAGE;
            qkv_issue(a_base + s * AW_WORDS * 4, b_base + s * BW_WORDS * 4,
                      mt, Wp, h0, (ci + 2) * 64, tid);
            CP_COMMIT();
        }
        int s = ci % NSTAGE;
        gemm_mma_chunk(a_base + s * AW_WORDS * 4 + aoff,
                       BwB + s * BW_WORDS, acc, wn, lq, lr);
    }

#pragma unroll
    for (int mf = 0; mf < 4; mf++) {
#pragma unroll
        for (int nf = 0; nf < 4; nf++) {
            int row = wm * 64 + mf * 16 + lq;
            int col = wn * 32 + nf * 8 + 2 * lr;
            int h   = h0 + (col >> 6);
            int hs  = col & 63;
#pragma unroll
            for (int half = 0; half < 2; half++) {
                int gr = mt * 128 + row + half * 8;
                int b = gr >> 10, t = gr & 1023;
                __half2* dp = reinterpret_cast<__half2*>(
                    dst + ((size_t)(b * HH + h) * TT + t) * HSS + hs);
                *dp = __floats2half2_rn(acc[mf][nf][half * 2],
                                        acc[mf][nf][half * 2 + 1]);
            }
        }
    }
}

// ---------------------------------------------------------------------------
// Output projection: out[4096,1024] = g_att @ Wo + bo.  grid (32, 8).
// ---------------------------------------------------------------------------
__device__ __forceinline__ void proj_issue(
    uint32_t a_s, uint32_t b_s, int mt, int nt, int k0, int tid)
{
#pragma unroll
    for (int i = 0; i < 4; i++) {
        int u = tid + i * 256;
        int row = u >> 3;
        int q4  = u & 7;
        cp16(a_s + (row * AW_STRIDE + q4 * 4) * 4,
             &g_att[(size_t)(mt * 128 + row) * DD + k0 + q4 * 8]);
    }
#pragma unroll
    for (int i = 0; i < 4; i++) {
        int u = tid + i * 256;
        int kp = u >> 5;
        int n  = (u & 31) * 4;
        cp16(b_s + (kp * BW_STRIDE + n) * 4,
             &g_wop[((size_t)(k0 >> 1) + kp) * DD + nt * 128 + n]);
    }
}

__global__ __launch_bounds__(256, 2) void proj_kernel(
    const float* __restrict__ bo, float* __restrict__ out)
{
    extern __shared__ unsigned dsm[];
    unsigned* AwB = dsm;
    unsigned* BwB = dsm + NSTAGE * AW_WORDS;
    const uint32_t a_base = smem_u32(AwB);
    const uint32_t b_base = smem_u32(BwB);

    const int mt = blockIdx.x;
    const int nt = blockIdx.y;

    const int tid  = threadIdx.x;
    const int lane = tid & 31;
    const int warp = tid >> 5;
    const int wm   = warp >> 2;
    const int wn   = warp & 3;
    const int lq   = lane >> 2;
    const int lr   = lane & 3;
    const uint32_t aoff = (uint32_t)(wm * 64 * AW_STRIDE) * 4 + a_lane_off(lane);

    float acc[4][4][4];
#pragma unroll
    for (int mf = 0; mf < 4; mf++)
#pragma unroll
        for (int nf = 0; nf < 4; nf++)
#pragma unroll
            for (int j = 0; j < 4; j++) acc[mf][nf][j] = 0.f;

    proj_issue(a_base, b_base, mt, nt, 0, tid);
    CP_COMMIT();
    proj_issue(a_base + AW_WORDS * 4, b_base + BW_WORDS * 4, mt, nt, 64, tid);
    CP_COMMIT();

    for (int ci = 0; ci < NCHUNK; ci++) {
        if (ci < NCHUNK - 2) CP_WAIT1(); else CP_WAIT0();
        __syncthreads();
        if (ci + 2 < NCHUNK) {
            int s = (ci + 2) % NSTAGE;
            proj_issue(a_base + s * AW_WORDS * 4, b_base + s * BW_WORDS * 4,
                       mt, nt, (ci + 2) * 64, tid);
            CP_COMMIT();
        }
        int s = ci % NSTAGE;
        gemm_mma_chunk(a_base + s * AW_WORDS * 4 + aoff,
                       BwB + s * BW_WORDS, acc, wn, lq, lr);
    }

#pragma unroll
    for (int mf = 0; mf < 4; mf++) {
#pragma unroll
        for (int nf = 0; nf < 4; nf++) {
            int row = wm * 64 + mf * 16 + lq;
            int col = nt * 128 + wn * 32 + nf * 8 + 2 * lr;
            float b0 = bo[col], b1 = bo[col + 1];
            float* C0 = out + (size_t)(mt * 128 + row) * DD + col;
            float* C1 = out + (size_t)(mt * 128 + row + 8) * DD + col;
            *reinterpret_cast<float2*>(C0) =
                make_float2(acc[mf][nf][0] + b0, acc[mf][nf][1] + b1);
            *reinterpret_cast<float2*>(C1) =
                make_float2(acc[mf][nf][2] + b0, acc[mf][nf][3] + b1);
        }
    }
}

// ---------------------------------------------------------------------------
// Causal flash attention, fp16 m16n8k16. Block = 256 threads (8 warps),
// q-tile 128; warp w owns rows [16w, 16w+16). kv tiles of 64.
// cp.async double-buffered K + raw-V prefetch; V perm is smem->smem.
// Dynamic smem: Qs[128*36] | Ks[2][64*36] | Vr[2][64*36] | Vs[32*72]
// ---------------------------------------------------------------------------
#define ATQ_WORDS (128 * 36)            // 4608
#define ATK_WORDS (64 * 36)             // 2304
#define ATV_WORDS (32 * 72)             // 2304
#define ATTN_SMEM ((ATQ_WORDS + 2 * ATK_WORDS + 2 * ATK_WORDS + ATV_WORDS) * 4) // 64512

__global__ __launch_bounds__(256) void attn_kernel()
{
    extern __shared__ unsigned sdyn[];
    unsigned* Qs  = sdyn;
    unsigned* KsB = sdyn + ATQ_WORDS;                    // 2 buffers
    unsigned* VrB = sdyn + ATQ_WORDS + 2 * ATK_WORDS;    // 2 buffers (raw V)
    unsigned* Vs  = sdyn + ATQ_WORDS + 4 * ATK_WORDS;    // single (perm'd)

    const int it = gridDim.x - 1 - blockIdx.x;   // heavy tiles first
    const int bh = blockIdx.y;
    const int b = bh >> 4, h = bh & 15;

    const __half* Q  = g_q + (size_t)bh * TT * HSS + (size_t)it * 128 * HSS;
    const __half* Kg = g_k + (size_t)bh * TT * HSS;
    const __half* Vg = g_v + (size_t)bh * TT * HSS;

    const int tid  = threadIdx.x;
    const int lane = tid & 31;
    const int warp = tid >> 5;
    const int lq   = lane >> 2;
    const int lr   = lane & 3;
    const int mrow = warp * 16 + lq;

    const uint32_t ks_base = smem_u32(KsB);
    const uint32_t vr_base = smem_u32(VrB);
    const uint32_t q_addr0 = smem_u32(Qs) + (uint32_t)(warp * 16 * 36) * 4 + a_lane_off(lane);
    const int krow_l = (lane & 7) + ((lane >> 4) & 1) * 8;
    const int kcol_l = ((lane >> 3) & 1) * 4;

    const int ld_row0 = tid >> 3;          // 0..31
    const int ld_u    = tid & 7;           // 0..7

    // Load Q tile: 128 rows x 8 uint4 (once per block)
#pragma unroll
    for (int i = 0; i < 4; i++) {
        int l = tid + i * 256;
        int row = l >> 3;
        int u   = l & 7;
        uint4 v = *reinterpret_cast<const uint4*>(&Q[(size_t)row * HSS + u * 8]);
        *reinterpret_cast<uint4*>(&Qs[row * 36 + u * 4]) = v;
    }

    const int ntiles = 2 * it + 2;

    // prologue: issue tile 0 into buffer 0
    {
        uint32_t kd = ks_base;
        uint32_t vd = vr_base;
#pragma unroll
        for (int i = 0; i < 2; i++) {
            int row = ld_row0 + i * 32;
            cp16(kd + (uint32_t)(row * 36 + ld_u * 4) * 4, &Kg[(size_t)row * HSS + ld_u * 8]);
            cp16(vd + (uint32_t)(row * 36 + ld_u * 4) * 4, &Vg[(size_t)row * HSS + ld_u * 8]);
        }
        CP_COMMIT();
    }

    float m0 = -1e30f, m1 = -1e30f, l0 = 0.f, l1 = 0.f;
    float o[8][4];
#pragma unroll
    for (int j = 0; j < 8; j++)
#pragma unroll
        for (int c = 0; c < 4; c++) o[j][c] = 0.f;

    for (int jt = 0; jt < ntiles; jt++) {
        const int buf  = jt & 1;
        if (jt + 1 < ntiles) {
            const __half* Kn = Kg + (size_t)(jt + 1) * 64 * HSS;
            const __half* Vn = Vg + (size_t)(jt + 1) * 64 * HSS;
            uint32_t kd = ks_base + (uint32_t)((1 - buf) * ATK_WORDS) * 4;
            uint32_t vd = vr_base + (uint32_t)((1 - buf) * ATK_WORDS) * 4;
#pragma unroll
            for (int i = 0; i < 2; i++) {
                int row = ld_row0 + i * 32;
                cp16(kd + (uint32_t)(row * 36 + ld_u * 4) * 4, &Kn[(size_t)row * HSS + ld_u * 8]);
                cp16(vd + (uint32_t)(row * 36 + ld_u * 4) * 4, &Vn[(size_t)row * HSS + ld_u * 8]);
            }
            CP_COMMIT();
            CP_WAIT1();
        } else {
            CP_WAIT0();
        }
        __syncthreads();   // current K/Vr visible; all warps done with prior Vs

        // perm raw V -> Vs (smem -> smem)
        {
            const unsigned* Vr = VrB + buf * ATK_WORDS;
            int kp = tid >> 3;
            int no = tid & 7;
            uint4 r0 = *reinterpret_cast<const uint4*>(&Vr[(2 * kp) * 36 + no * 4]);
            uint4 r1 = *reinterpret_cast<const uint4*>(&Vr[(2 * kp + 1) * 36 + no * 4]);
            uint4 w0, w1;
            w0.x = __byte_perm(r0.x, r1.x, 0x5410);
            w0.y = __byte_perm(r0.x, r1.x, 0x7632);
            w0.z = __byte_perm(r0.y, r1.y, 0x5410);
            w0.w = __byte_perm(r0.y, r1.y, 0x7632);
            w1.x = __byte_perm(r0.z, r1.z, 0x5410);
            w1.y = __byte_perm(r0.z, r1.z, 0x7632);
            w1.z = __byte_perm(r0.w, r1.w, 0x5410);
            w1.w = __byte_perm(r0.w, r1.w, 0x7632);
            *reinterpret_cast<uint4*>(&Vs[kp * 72 + no * 8])     = w0;
            *reinterpret_cast<uint4*>(&Vs[kp * 72 + no * 8 + 4]) = w1;
        }
        __syncthreads();   // Vs ready

        if (jt == 2 * it + 1 && warp < 4) continue;

        const uint32_t k_addr0 = ks_base + (uint32_t)(buf * ATK_WORDS) * 4
                               + (uint32_t)(krow_l * 36 + kcol_l) * 4;

        // ---- S = Q K^T
        float s[8][4];
#pragma unroll
        for (int j = 0; j < 8; j++)
#pragma unroll
            for (int c = 0; c < 4; c++) s[j][c] = 0.f;

#pragma unroll
        for (int c = 0; c < 4; c++) {
            unsigned a[4];
            ldsm4(a[0], a[1], a[2], a[3], q_addr0 + (uint32_t)(c * 8) * 4);
#pragma unroll
            for (int jp = 0; jp < 4; jp++) {
                unsigned b0, b1, b2, b3;
                ldsm4(b0, b1, b2, b3,
                      k_addr0 + (uint32_t)(jp * 16 * 36 + c * 8) * 4);
                unsigned bb0[2] = {b0, b1};
                unsigned bb1[2] = {b2, b3};
                mma16h(s[2 * jp],     a, bb0);
                mma16h(s[2 * jp + 1], a, bb1);
            }
        }

        const float scale = 0.125f;
#pragma unroll
        for (int j = 0; j < 8; j++)
#pragma unroll
            for (int c = 0; c < 4; c++) s[j][c] *= scale;

        if (jt >= 2 * it) {
            int gr0 = it * 128 + mrow, gr1 = gr0 + 8;
            int gc_base = jt * 64;
#pragma unroll
            for (int j = 0; j < 8; j++) {
                int c0 = gc_base + j * 8 + 2 * lr, c1 = c0 + 1;
                if (c0 > gr0) s[j][0] = -1e30f;
                if (c1 > gr0) s[j][1] = -1e30f;
                if (c0 > gr1) s[j][2] = -1e30f;
                if (c1 > gr1) s[j][3] = -1e30f;
            }
        }

        // ---- online softmax
        float mx0 = -1e30f, mx1 = -1e30f;
#pragma unroll
        for (int j = 0; j < 8; j++) {
            mx0 = fmaxf(mx0, fmaxf(s[j][0], s[j][1]));
            mx1 = fmaxf(mx1, fmaxf(s[j][2], s[j][3]));
        }
        mx0 = fmaxf(mx0, __shfl_xor_sync(0xffffffffu, mx0, 1));
        mx0 = fmaxf(mx0, __shfl_xor_sync(0xffffffffu, mx0, 2));
        mx1 = fmaxf(mx1, __shfl_xor_sync(0xffffffffu, mx1, 1));
        mx1 = fmaxf(mx1, __shfl_xor_sync(0xffffffffu, mx1, 2));

        float mn0 = fmaxf(m0, mx0), mn1 = fmaxf(m1, mx1);
        float f0 = __expf(m0 - mn0), f1 = __expf(m1 - mn1);

        float rs0 = 0.f, rs1 = 0.f;
#pragma unroll
        for (int j = 0; j < 8; j++) {
            s[j][0] = __expf(s[j][0] - mn0);
            s[j][1] = __expf(s[j][1] - mn0);
            s[j][2] = __expf(s[j][2] - mn1);
            s[j][3] = __expf(s[j][3] - mn1);
            rs0 += s[j][0] + s[j][1];
            rs1 += s[j][2] + s[j][3];
        }
        rs0 += __shfl_xor_sync(0xffffffffu, rs0, 1);
        rs0 += __shfl_xor_sync(0xffffffffu, rs0, 2);
        rs1 += __shfl_xor_sync(0xffffffffu, rs1, 1);
        rs1 += __shfl_xor_sync(0xffffffffu, rs1, 2);

        l0 = l0 * f0 + rs0;
        l1 = l1 * f1 + rs1;
        m0 = mn0; m1 = mn1;
#pragma unroll
        for (int j = 0; j < 8; j++) {
            o[j][0] *= f0; o[j][1] *= f0;
            o[j][2] *= f1; o[j][3] *= f1;
        }

        // ---- O += P V  (P packed from registers)
#pragma unroll
        for (int c = 0; c < 4; c++) {
            unsigned a[4];
            a[0] = packh2(s[2 * c][0],     s[2 * c][1]);
            a[1] = packh2(s[2 * c][2],     s[2 * c][3]);
            a[2] = packh2(s[2 * c + 1][0], s[2 * c + 1][1]);
            a[3] = packh2(s[2 * c + 1][2], s[2 * c + 1][3]);
            const int kb = c * 8 + lr;
#pragma unroll
            for (int j = 0; j < 8; j++) {
                unsigned bb[2];
                bb[0] = Vs[kb * 72 + j * 8 + lq];
                bb[1] = Vs[(kb + 4) * 72 + j * 8 + lq];
                mma16h(o[j], a, bb);
            }
        }
    }

    float inv0 = 1.f / l0, inv1 = 1.f / l1;
    size_t row0 = (size_t)b * TT + (size_t)it * 128 + mrow;
    size_t row1 = row0 + 8;
#pragma unroll
    for (int j = 0; j < 8; j++) {
        int cb = h * HSS + j * 8 + 2 * lr;
        *reinterpret_cast<__half2*>(&g_att[row0 * DD + cb]) =
            __floats2half2_rn(o[j][0] * inv0, o[j][1] * inv0);
        *reinterpret_cast<__half2*>(&g_att[row1 * DD + cb]) =
            __floats2half2_rn(o[j][2] * inv1, o[j][3] * inv1);
    }
}

extern "C" void kernel_launch(void* const* d_in, const int* in_sizes, int n_in,
                              void* d_out, int out_size)
{
    const float* x  = (const float*)d_in[0];
    const float* Wq = (const float*)d_in[1];
    const float* Wk = (const float*)d_in[2];
    const float* Wv = (const float*)d_in[3];
    const float* Wo = (const float*)d_in[4];
    const float* bo = (const float*)d_in[5];
    float* out = (float*)d_out;

    cudaFuncSetAttribute(qkv_kernel,
                         cudaFuncAttributeMaxDynamicSharedMemorySize, PIPE_SMEM);
    cudaFuncSetAttribute(proj_kernel,
                         cudaFuncAttributeMaxDynamicSharedMemorySize, PIPE_SMEM);
    cudaFuncSetAttribute(attn_kernel,
                         cudaFuncAttributeMaxDynamicSharedMemorySize, ATTN_SMEM);

    // Fork stream + events (host objects; intentionally leaked — replays run
    // only the captured graph).
    cudaStream_t s1;
    cudaStreamCreateWithFlags(&s1, cudaStreamNonBlocking);
    cudaEvent_t e0, ej;
    cudaEventCreateWithFlags(&e0, cudaEventDisableTiming);
    cudaEventCreateWithFlags(&ej, cudaEventDisableTiming);

    conv_main<<<512, 256>>>(x, Wq, Wk, Wv);

    // Fork: Wo pack overlaps qkv/attn; joined before proj.
    cudaEventRecord(e0, 0);
    cudaStreamWaitEvent(s1, e0, 0);
    conv_wo<<<256, 256, 0, s1>>>(Wo);
    cudaEventRecord(ej, s1);

    dim3 g1(24, (BB * TT) / 128);
    qkv_kernel<<<g1, 256, PIPE_SMEM>>>();

    dim3 g2(TT / 128, BB * HH);
    attn_kernel<<<g2, 256, ATTN_SMEM>>>();

    cudaStreamWaitEvent(0, ej, 0);   // join before proj
    dim3 g3((BB * TT) / 128, DD / 128);
    proj_kernel<<<g3, 256, PIPE_SMEM>>>(bo, out);
}

// round 16
// speedup vs baseline: 1.0130x; 1.0130x over previous
#include <cuda_runtime.h>
#include <cuda_fp16.h>
#include <math.h>
#include <cstdint>

#define BB 4
#define TT 1024
#define DD 1024
#define HH 16
#define HSS 64

// Scratch (no cudaMalloc allowed)
__device__ __align__(16) __half g_xh[BB*TT*DD];            // x in fp16
__device__ __align__(16) unsigned g_wp[3*HH*512*HSS];      // W q/k/v paired: [which][h][kp][hs]
__device__ __align__(16) unsigned g_wop[512*DD];           // Wo paired: [kp][n]
__device__ __align__(16) __half g_q[BB*HH*TT*HSS];         // pre-scaled by 0.125*log2e
__device__ __align__(16) __half g_k[BB*HH*TT*HSS];
__device__ __align__(16) __half g_v[BB*HH*TT*HSS];
__device__ __align__(16) __half g_att[BB*TT*DD];

// ---------------------------------------------------------------------------
// helpers
// ---------------------------------------------------------------------------
__device__ __forceinline__ void mma16h(float* d, const unsigned* a, const unsigned* b) {
    asm volatile(
        "mma.sync.aligned.m16n8k16.row.col.f32.f16.f16.f32 "
        "{%0,%1,%2,%3}, {%4,%5,%6,%7}, {%8,%9}, {%0,%1,%2,%3};"
        : "+f"(d[0]), "+f"(d[1]), "+f"(d[2]), "+f"(d[3])
        : "r"(a[0]), "r"(a[1]), "r"(a[2]), "r"(a[3]),
          "r"(b[0]), "r"(b[1]));
}

__device__ __forceinline__ void ldsm4(unsigned& r0, unsigned& r1,
                                      unsigned& r2, unsigned& r3, uint32_t addr) {
    asm volatile("ldmatrix.sync.aligned.m8n8.x4.shared.b16 {%0,%1,%2,%3}, [%4];"
                 : "=r"(r0), "=r"(r1), "=r"(r2), "=r"(r3) : "r"(addr));
}

__device__ __forceinline__ unsigned packh2(float a, float b) {
    __half2 h = __floats2half2_rn(a, b);
    return *reinterpret_cast<unsigned*>(&h);
}

__device__ __forceinline__ uint32_t smem_u32(const void* p) {
    uint32_t a;
    asm("{ .reg .u64 t; cvta.to.shared.u64 t, %1; cvt.u32.u64 %0, t; }"
        : "=r"(a) : "l"(p));
    return a;
}

__device__ __forceinline__ void cp16(uint32_t s, const void* g) {
    asm volatile("cp.async.cg.shared.global [%0], [%1], 16;"
                 :: "r"(s), "l"(g) : "memory");
}
#define CP_COMMIT() asm volatile("cp.async.commit_group;" ::: "memory")
#define CP_WAIT1()  asm volatile("cp.async.wait_group 1;" ::: "memory")
#define CP_WAIT0()  asm volatile("cp.async.wait_group 0;" ::: "memory")

// 0.125 (HS^-0.5) * log2(e): folded into Q so softmax runs in exp2 domain.
#define QSCALE 0.180336880f

// ---------------------------------------------------------------------------
// Convert/pack kernel (vectorized)
// ---------------------------------------------------------------------------
__global__ void conv_kernel(const float* __restrict__ x,
                            const float* __restrict__ Wq,
                            const float* __restrict__ Wk,
                            const float* __restrict__ Wv,
                            const float* __restrict__ Wo)
{
    const int stride = gridDim.x * blockDim.x;
    const int tid0 = blockIdx.x * blockDim.x + threadIdx.x;

    const int XN8 = (BB * TT * DD) / 8;
    for (int i = tid0; i < XN8; i += stride) {
        float4 v0 = reinterpret_cast<const float4*>(x)[2 * i];
        float4 v1 = reinterpret_cast<const float4*>(x)[2 * i + 1];
        uint4 o;
        o.x = packh2(v0.x, v0.y);
        o.y = packh2(v0.z, v0.w);
        o.z = packh2(v1.x, v1.y);
        o.w = packh2(v1.z, v1.w);
        reinterpret_cast<uint4*>(g_xh)[i] = o;
    }

    const int WP4 = (3 * HH * 512 * HSS) / 4;
    for (int i = tid0; i < WP4; i += stride) {
        int w0 = i * 4;
        int hs = w0 & 63;
        int kp = (w0 >> 6) & 511;
        int h  = (w0 >> 15) & 15;
        int which = w0 >> 19;
        const float* W = (which == 0 ? Wq : which == 1 ? Wk : Wv);
        const float* s0 = W + ((size_t)h * DD + 2 * kp) * HSS + hs;
        float4 a = *reinterpret_cast<const float4*>(s0);
        float4 b = *reinterpret_cast<const float4*>(s0 + HSS);
        uint4 o;
        o.x = packh2(a.x, b.x); o.y = packh2(a.y, b.y);
        o.z = packh2(a.z, b.z); o.w = packh2(a.w, b.w);
        reinterpret_cast<uint4*>(g_wp)[i] = o;
    }

    const int WO4 = (512 * DD) / 4;
    for (int i = tid0; i < WO4; i += stride) {
        int w0 = i * 4;
        int n  = w0 & 1023;
        int kp = w0 >> 10;
        const float* s0 = Wo + (size_t)(2 * kp) * DD + n;
        float4 a = *reinterpret_cast<const float4*>(s0);
        float4 b = *reinterpret_cast<const float4*>(s0 + DD);
        uint4 o;
        o.x = packh2(a.x, b.x); o.y = packh2(a.y, b.y);
        o.z = packh2(a.z, b.z); o.w = packh2(a.w, b.w);
        reinterpret_cast<uint4*>(g_wop)[i] = o;
    }
}

// ---------------------------------------------------------------------------
// fp16 GEMM: block 128x128, 8 warps = 2(m) x 4(n), warp 64x32, BK=64.
// Aw[row 128][kp 32 + pad4]  -> ldmatrix.x4 for A fragments
// Bw[kp 32][n 128 + pad8]    -> scalar frags (packed k-pairs)
// 3-stage cp.async pipeline, 16 k-chunks.
// ---------------------------------------------------------------------------
#define AW_STRIDE 36
#define BW_STRIDE 136
#define AW_WORDS  (128 * AW_STRIDE)     // 4608
#define BW_WORDS  (32 * BW_STRIDE)      // 4352
#define NSTAGE 3
#define NCHUNK 16
#define PIPE_SMEM ((AW_WORDS + BW_WORDS) * NSTAGE * 4)   // 107520 bytes

__device__ __forceinline__ uint32_t a_lane_off(int lane) {
    int r = (lane & 7) + ((lane >> 3) & 1) * 8;
    int c = (lane & 16) ? 4 : 0;
    return (uint32_t)(r * AW_STRIDE + c) * 4;
}

__device__ __forceinline__ void gemm_mma_chunk(
    uint32_t aw_addr0, const unsigned* __restrict__ Bw,
    float acc[4][4][4], int wn, int lq, int lr)
{
#pragma unroll
    for (int kc = 0; kc < 4; kc++) {
        const int kb = kc * 8 + lr;
        unsigned a[4][4];
#pragma unroll
        for (int mf = 0; mf < 4; mf++)
            ldsm4(a[mf][0], a[mf][1], a[mf][2], a[mf][3],
                  aw_addr0 + (uint32_t)(mf * 16 * AW_STRIDE + kc * 8) * 4);
        unsigned b[4][2];
#pragma unroll
        for (int nf = 0; nf < 4; nf++) {
            int nc = wn * 32 + nf * 8 + lq;
            b[nf][0] = Bw[kb * BW_STRIDE + nc];
            b[nf][1] = Bw[(kb + 4) * BW_STRIDE + nc];
        }
#pragma unroll
        for (int mf = 0; mf < 4; mf++)
#pragma unroll
            for (int nf = 0; nf < 4; nf++)
                mma16h(acc[mf][nf], a[mf], b[nf]);
    }
}

// ---------------------------------------------------------------------------
// QKV: logical GEMM [4096 x 3072 x 1024]. grid (24, 32): x = nt (fast), y = mt.
// Q outputs are pre-scaled by QSCALE (softmax scale folded in).
// ---------------------------------------------------------------------------
__device__ __forceinline__ void qkv_issue(
    uint32_t a_s, uint32_t b_s, int mt, const unsigned* Wp, int h0, int k0, int tid)
{
#pragma unroll
    for (int i = 0; i < 4; i++) {
        int u = tid + i * 256;
        int row = u >> 3;
        int q4  = u & 7;
        cp16(a_s + (row * AW_STRIDE + q4 * 4) * 4,
             &g_xh[(size_t)(mt * 128 + row) * DD + k0 + q4 * 8]);
    }
#pragma unroll
    for (int i = 0; i < 4; i++) {
        int u = tid + i * 256;
        int kp = u >> 5;
        int n  = (u & 31) * 4;
        int h  = h0 + (n >> 6);
        int hs = n & 63;
        cp16(b_s + (kp * BW_STRIDE + n) * 4,
             &Wp[((size_t)h * 512 + (k0 >> 1) + kp) * HSS + hs]);
    }
}

__global__ __launch_bounds__(256, 2) void qkv_kernel()
{
    extern __shared__ unsigned dsm[];
    unsigned* AwB = dsm;
    unsigned* BwB = dsm + NSTAGE * AW_WORDS;
    const uint32_t a_base = smem_u32(AwB);
    const uint32_t b_base = smem_u32(BwB);

    const int nt = blockIdx.x;           // 0..23
    const int mt = blockIdx.y;           // 0..31
    const int which = nt >> 3;
    const int h0 = (nt & 7) * 2;

    __half* dst = (which == 0 ? g_q : which == 1 ? g_k : g_v);
    const unsigned* Wp = g_wp + (size_t)which * HH * 512 * HSS;
    const float oscale = (which == 0) ? QSCALE : 1.0f;

    const int tid  = threadIdx.x;
    const int lane = tid & 31;
    const int warp = tid >> 5;
    const int wm   = warp >> 2;
    const int wn   = warp & 3;
    const int lq   = lane >> 2;
    const int lr   = lane & 3;
    const uint32_t aoff = (uint32_t)(wm * 64 * AW_STRIDE) * 4 + a_lane_off(lane);

    float acc[4][4][4];
#pragma unroll
    for (int mf = 0; mf < 4; mf++)
#pragma unroll
        for (int nf = 0; nf < 4; nf++)
#pragma unroll
            for (int j = 0; j < 4; j++) acc[mf][nf][j] = 0.f;

    qkv_issue(a_base, b_base, mt, Wp, h0, 0, tid);
    CP_COMMIT();
    qkv_issue(a_base + AW_WORDS * 4, b_base + BW_WORDS * 4, mt, Wp, h0, 64, tid);
    CP_COMMIT();

    for (int ci = 0; ci < NCHUNK; ci++) {
        if (ci < NCHUNK - 2) CP_WAIT1(); else CP_WAIT0();
        __syncthreads();
        if (ci + 2 < NCHUNK) {
            int s = (ci + 2) % NSTAGE;
            qkv_issue(a_base + s * AW_WORDS * 4, b_base + s * BW_WORDS * 4,
                      mt, Wp, h0, (ci + 2) * 64, tid);
            CP_COMMIT();
        }
        int s = ci % NSTAGE;
        gemm_mma_chunk(a_base + s * AW_WORDS * 4 + aoff,
                       BwB + s * BW_WORDS, acc, wn, lq, lr);
    }

#pragma unroll
    for (int mf = 0; mf < 4; mf++) {
#pragma unroll
        for (int nf = 0; nf < 4; nf++) {
            int row = wm * 64 + mf * 16 + lq;
            int col = wn * 32 + nf * 8 + 2 * lr;
            int h   = h0 + (col >> 6);
            int hs  = col & 63;
#pragma unroll
            for (int half = 0; half < 2; half++) {
                int gr = mt * 128 + row + half * 8;
                int b = gr >> 10, t = gr & 1023;
                __half2* dp = reinterpret_cast<__half2*>(
                    dst + ((size_t)(b * HH + h) * TT + t) * HSS + hs);
                *dp = __floats2half2_rn(acc[mf][nf][half * 2] * oscale,
                                        acc[mf][nf][half * 2 + 1] * oscale);
            }
        }
    }
}

// ---------------------------------------------------------------------------
// Output projection: out[4096,1024] = g_att @ Wo + bo.  grid (32, 8).
// ---------------------------------------------------------------------------
__device__ __forceinline__ void proj_issue(
    uint32_t a_s, uint32_t b_s, int mt, int nt, int k0, int tid)
{
#pragma unroll
    for (int i = 0; i < 4; i++) {
        int u = tid + i * 256;
        int row = u >> 3;
        int q4  = u & 7;
        cp16(a_s + (row * AW_STRIDE + q4 * 4) * 4,
             &g_att[(size_t)(mt * 128 + row) * DD + k0 + q4 * 8]);
    }
#pragma unroll
    for (int i = 0; i < 4; i++) {
        int u = tid + i * 256;
        int kp = u >> 5;
        int n  = (u & 31) * 4;
        cp16(b_s + (kp * BW_STRIDE + n) * 4,
             &g_wop[((size_t)(k0 >> 1) + kp) * DD + nt * 128 + n]);
    }
}

__global__ __launch_bounds__(256, 2) void proj_kernel(
    const float* __restrict__ bo, float* __restrict__ out)
{
    extern __shared__ unsigned dsm[];
    unsigned* AwB = dsm;
    unsigned* BwB = dsm + NSTAGE * AW_WORDS;
    const uint32_t a_base = smem_u32(AwB);
    const uint32_t b_base = smem_u32(BwB);

    const int mt = blockIdx.x;
    const int nt = blockIdx.y;

    const int tid  = threadIdx.x;
    const int lane = tid & 31;
    const int warp = tid >> 5;
    const int wm   = warp >> 2;
    const int wn   = warp & 3;
    const int lq   = lane >> 2;
    const int lr   = lane & 3;
    const uint32_t aoff = (uint32_t)(wm * 64 * AW_STRIDE) * 4 + a_lane_off(lane);

    float acc[4][4][4];
#pragma unroll
    for (int mf = 0; mf < 4; mf++)
#pragma unroll
        for (int nf = 0; nf < 4; nf++)
#pragma unroll
            for (int j = 0; j < 4; j++) acc[mf][nf][j] = 0.f;

    proj_issue(a_base, b_base, mt, nt, 0, tid);
    CP_COMMIT();
    proj_issue(a_base + AW_WORDS * 4, b_base + BW_WORDS * 4, mt, nt, 64, tid);
    CP_COMMIT();

    for (int ci = 0; ci < NCHUNK; ci++) {
        if (ci < NCHUNK - 2) CP_WAIT1(); else CP_WAIT0();
        __syncthreads();
        if (ci + 2 < NCHUNK) {
            int s = (ci + 2) % NSTAGE;
            proj_issue(a_base + s * AW_WORDS * 4, b_base + s * BW_WORDS * 4,
                       mt, nt, (ci + 2) * 64, tid);
            CP_COMMIT();
        }
        int s = ci % NSTAGE;
        gemm_mma_chunk(a_base + s * AW_WORDS * 4 + aoff,
                       BwB + s * BW_WORDS, acc, wn, lq, lr);
    }

#pragma unroll
    for (int mf = 0; mf < 4; mf++) {
#pragma unroll
        for (int nf = 0; nf < 4; nf++) {
            int row = wm * 64 + mf * 16 + lq;
            int col = nt * 128 + wn * 32 + nf * 8 + 2 * lr;
            float b0 = bo[col], b1 = bo[col + 1];
            float* C0 = out + (size_t)(mt * 128 + row) * DD + col;
            float* C1 = out + (size_t)(mt * 128 + row + 8) * DD + col;
            *reinterpret_cast<float2*>(C0) =
                make_float2(acc[mf][nf][0] + b0, acc[mf][nf][1] + b1);
            *reinterpret_cast<float2*>(C1) =
                make_float2(acc[mf][nf][2] + b0, acc[mf][nf][3] + b1);
        }
    }
}

// ---------------------------------------------------------------------------
// Causal flash attention, fp16 m16n8k16. Block = 256 threads (8 warps),
// q-tile 128; warp w owns rows [16w, 16w+16). kv tiles of 64.
// Q pre-scaled by 0.125*log2e -> softmax in exp2 domain (no scale mul, bare EX2).
// cp.async double-buffered K + raw-V prefetch; V perm is smem->smem.
// ---------------------------------------------------------------------------
#define ATQ_WORDS (128 * 36)            // 4608
#define ATK_WORDS (64 * 36)             // 2304
#define ATV_WORDS (32 * 72)             // 2304
#define ATTN_SMEM ((ATQ_WORDS + 2 * ATK_WORDS + 2 * ATK_WORDS + ATV_WORDS) * 4) // 64512

__global__ __launch_bounds__(256) void attn_kernel()
{
    extern __shared__ unsigned sdyn[];
    unsigned* Qs  = sdyn;
    unsigned* KsB = sdyn + ATQ_WORDS;                    // 2 buffers
    unsigned* VrB = sdyn + ATQ_WORDS + 2 * ATK_WORDS;    // 2 buffers (raw V)
    unsigned* Vs  = sdyn + ATQ_WORDS + 4 * ATK_WORDS;    // single (perm'd)

    const int it = gridDim.x - 1 - blockIdx.x;   // heavy tiles first
    const int bh = blockIdx.y;
    const int b = bh >> 4, h = bh & 15;

    const __half* Q  = g_q + (size_t)bh * TT * HSS + (size_t)it * 128 * HSS;
    const __half* Kg = g_k + (size_t)bh * TT * HSS;
    const __half* Vg = g_v + (size_t)bh * TT * HSS;

    const int tid  = threadIdx.x;
    const int lane = tid & 31;
    const int warp = tid >> 5;
    const int lq   = lane >> 2;
    const int lr   = lane & 3;
    const int mrow = warp * 16 + lq;

    const uint32_t ks_base = smem_u32(KsB);
    const uint32_t vr_base = smem_u32(VrB);
    const uint32_t q_addr0 = smem_u32(Qs) + (uint32_t)(warp * 16 * 36) * 4 + a_lane_off(lane);
    const int krow_l = (lane & 7) + ((lane >> 4) & 1) * 8;
    const int kcol_l = ((lane >> 3) & 1) * 4;

    const int ld_row0 = tid >> 3;          // 0..31
    const int ld_u    = tid & 7;           // 0..7

    // Load Q tile: 128 rows x 8 uint4 (once per block)
#pragma unroll
    for (int i = 0; i < 4; i++) {
        int l = tid + i * 256;
        int row = l >> 3;
        int u   = l & 7;
        uint4 v = *reinterpret_cast<const uint4*>(&Q[(size_t)row * HSS + u * 8]);
        *reinterpret_cast<uint4*>(&Qs[row * 36 + u * 4]) = v;
    }

    const int ntiles = 2 * it + 2;

    // prologue: issue tile 0 into buffer 0
    {
        uint32_t kd = ks_base;
        uint32_t vd = vr_base;
#pragma unroll
        for (int i = 0; i < 2; i++) {
            int row = ld_row0 + i * 32;
            cp16(kd + (uint32_t)(row * 36 + ld_u * 4) * 4, &Kg[(size_t)row * HSS + ld_u * 8]);
            cp16(vd + (uint32_t)(row * 36 + ld_u * 4) * 4, &Vg[(size_t)row * HSS + ld_u * 8]);
        }
        CP_COMMIT();
    }

    float m0 = -1e30f, m1 = -1e30f, l0 = 0.f, l1 = 0.f;
    float o[8][4];
#pragma unroll
    for (int j = 0; j < 8; j++)
#pragma unroll
        for (int c = 0; c < 4; c++) o[j][c] = 0.f;

    for (int jt = 0; jt < ntiles; jt++) {
        const int buf  = jt & 1;
        if (jt + 1 < ntiles) {
            const __half* Kn = Kg + (size_t)(jt + 1) * 64 * HSS;
            const __half* Vn = Vg + (size_t)(jt + 1) * 64 * HSS;
            uint32_t kd = ks_base + (uint32_t)((1 - buf) * ATK_WORDS) * 4;
            uint32_t vd = vr_base + (uint32_t)((1 - buf) * ATK_WORDS) * 4;
#pragma unroll
            for (int i = 0; i < 2; i++) {
                int row = ld_row0 + i * 32;
                cp16(kd + (uint32_t)(row * 36 + ld_u * 4) * 4, &Kn[(size_t)row * HSS + ld_u * 8]);
                cp16(vd + (uint32_t)(row * 36 + ld_u * 4) * 4, &Vn[(size_t)row * HSS + ld_u * 8]);
            }
            CP_COMMIT();
            CP_WAIT1();
        } else {
            CP_WAIT0();
        }
        __syncthreads();   // current K/Vr visible; all warps done with prior Vs

        // perm raw V -> Vs (smem -> smem)
        {
            const unsigned* Vr = VrB + buf * ATK_WORDS;
            int kp = tid >> 3;
            int no = tid & 7;
            uint4 r0 = *reinterpret_cast<const uint4*>(&Vr[(2 * kp) * 36 + no * 4]);
            uint4 r1 = *reinterpret_cast<const uint4*>(&Vr[(2 * kp + 1) * 36 + no * 4]);
            uint4 w0, w1;
            w0.x = __byte_perm(r0.x, r1.x, 0x5410);
            w0.y = __byte_perm(r0.x, r1.x, 0x7632);
            w0.z = __byte_perm(r0.y, r1.y, 0x5410);
            w0.w = __byte_perm(r0.y, r1.y, 0x7632);
            w1.x = __byte_perm(r0.z, r1.z, 0x5410);
            w1.y = __byte_perm(r0.z, r1.z, 0x7632);
            w1.z = __byte_perm(r0.w, r1.w, 0x5410);
            w1.w = __byte_perm(r0.w, r1.w, 0x7632);
            *reinterpret_cast<uint4*>(&Vs[kp * 72 + no * 8])     = w0;
            *reinterpret_cast<uint4*>(&Vs[kp * 72 + no * 8 + 4]) = w1;
        }
        __syncthreads();   // Vs ready

        if (jt == 2 * it + 1 && warp < 4) continue;

        const uint32_t k_addr0 = ks_base + (uint32_t)(buf * ATK_WORDS) * 4
                               + (uint32_t)(krow_l * 36 + kcol_l) * 4;

        // ---- S = Q K^T  (already scaled: log2-domain logits)
        float s[8][4];
#pragma unroll
        for (int j = 0; j < 8; j++)
#pragma unroll
            for (int c = 0; c < 4; c++) s[j][c] = 0.f;

#pragma unroll
        for (int c = 0; c < 4; c++) {
            unsigned a[4];
            ldsm4(a[0], a[1], a[2], a[3], q_addr0 + (uint32_t)(c * 8) * 4);
#pragma unroll
            for (int jp = 0; jp < 4; jp++) {
                unsigned b0, b1, b2, b3;
                ldsm4(b0, b1, b2, b3,
                      k_addr0 + (uint32_t)(jp * 16 * 36 + c * 8) * 4);
                unsigned bb0[2] = {b0, b1};
                unsigned bb1[2] = {b2, b3};
                mma16h(s[2 * jp],     a, bb0);
                mma16h(s[2 * jp + 1], a, bb1);
            }
        }

        if (jt >= 2 * it) {
            int gr0 = it * 128 + mrow, gr1 = gr0 + 8;
            int gc_base = jt * 64;
#pragma unroll
            for (int j = 0; j < 8; j++) {
                int c0 = gc_base + j * 8 + 2 * lr, c1 = c0 + 1;
                if (c0 > gr0) s[j][0] = -1e30f;
                if (c1 > gr0) s[j][1] = -1e30f;
                if (c0 > gr1) s[j][2] = -1e30f;
                if (c1 > gr1) s[j][3] = -1e30f;
            }
        }

        // ---- online softmax (exp2 domain)
        float mx0 = -1e30f, mx1 = -1e30f;
#pragma unroll
        for (int j = 0; j < 8; j++) {
            mx0 = fmaxf(mx0, fmaxf(s[j][0], s[j][1]));
            mx1 = fmaxf(mx1, fmaxf(s[j][2], s[j][3]));
        }
        mx0 = fmaxf(mx0, __shfl_xor_sync(0xffffffffu, mx0, 1));
        mx0 = fmaxf(mx0, __shfl_xor_sync(0xffffffffu, mx0, 2));
        mx1 = fmaxf(mx1, __shfl_xor_sync(0xffffffffu, mx1, 1));
        mx1 = fmaxf(mx1, __shfl_xor_sync(0xffffffffu, mx1, 2));

        float mn0 = fmaxf(m0, mx0), mn1 = fmaxf(m1, mx1);
        float f0 = exp2f(m0 - mn0), f1 = exp2f(m1 - mn1);

        float rs0 = 0.f, rs1 = 0.f;
#pragma unroll
        for (int j = 0; j < 8; j++) {
            s[j][0] = exp2f(s[j][0] - mn0);
            s[j][1] = exp2f(s[j][1] - mn0);
            s[j][2] = exp2f(s[j][2] - mn1);
            s[j][3] = exp2f(s[j][3] - mn1);
            rs0 += s[j][0] + s[j][1];
            rs1 += s[j][2] + s[j][3];
        }
        rs0 += __shfl_xor_sync(0xffffffffu, rs0, 1);
        rs0 += __shfl_xor_sync(0xffffffffu, rs0, 2);
        rs1 += __shfl_xor_sync(0xffffffffu, rs1, 1);
        rs1 += __shfl_xor_sync(0xffffffffu, rs1, 2);

        l0 = l0 * f0 + rs0;
        l1 = l1 * f1 + rs1;
        m0 = mn0; m1 = mn1;
#pragma unroll
        for (int j = 0; j < 8; j++) {
            o[j][0] *= f0; o[j][1] *= f0;
            o[j][2] *= f1; o[j][3] *= f1;
        }

        // ---- O += P V  (P packed from registers)
#pragma unroll
        for (int c = 0; c < 4; c++) {
            unsigned a[4];
            a[0] = packh2(s[2 * c][0],     s[2 * c][1]);
            a[1] = packh2(s[2 * c][2],     s[2 * c][3]);
            a[2] = packh2(s[2 * c + 1][0], s[2 * c + 1][1]);
            a[3] = packh2(s[2 * c + 1][2], s[2 * c + 1][3]);
            const int kb = c * 8 + lr;
#pragma unroll
            for (int j = 0; j < 8; j++) {
                unsigned bb[2];
                bb[0] = Vs[kb * 72 + j * 8 + lq];
                bb[1] = Vs[(kb + 4) * 72 + j * 8 + lq];
                mma16h(o[j], a, bb);
            }
        }
    }

    float inv0 = 1.f / l0, inv1 = 1.f / l1;
    size_t row0 = (size_t)b * TT + (size_t)it * 128 + mrow;
    size_t row1 = row0 + 8;
#pragma unroll
    for (int j = 0; j < 8; j++) {
        int cb = h * HSS + j * 8 + 2 * lr;
        *reinterpret_cast<__half2*>(&g_att[row0 * DD + cb]) =
            __floats2half2_rn(o[j][0] * inv0, o[j][1] * inv0);
        *reinterpret_cast<__half2*>(&g_att[row1 * DD + cb]) =
            __floats2half2_rn(o[j][2] * inv1, o[j][3] * inv1);
    }
}

extern "C" void kernel_launch(void* const* d_in, const int* in_sizes, int n_in,
                              void* d_out, int out_size)
{
    const float* x  = (const float*)d_in[0];
    const float* Wq = (const float*)d_in[1];
    const float* Wk = (const float*)d_in[2];
    const float* Wv = (const float*)d_in[3];
    const float* Wo = (const float*)d_in[4];
    const float* bo = (const float*)d_in[5];
    float* out = (float*)d_out;

    cudaFuncSetAttribute(qkv_kernel,
                         cudaFuncAttributeMaxDynamicSharedMemorySize, PIPE_SMEM);
    cudaFuncSetAttribute(proj_kernel,
                         cudaFuncAttributeMaxDynamicSharedMemorySize, PIPE_SMEM);
    cudaFuncSetAttribute(attn_kernel,
                         cudaFuncAttributeMaxDynamicSharedMemorySize, ATTN_SMEM);

    conv_kernel<<<512, 256>>>(x, Wq, Wk, Wv, Wo);

    dim3 g1(24, (BB * TT) / 128);
    qkv_kernel<<<g1, 256, PIPE_SMEM>>>();

    dim3 g2(TT / 128, BB * HH);
    attn_kernel<<<g2, 256, ATTN_SMEM>>>();

    dim3 g3((BB * TT) / 128, DD / 128);
    proj_kernel<<<g3, 256, PIPE_SMEM>>>(bo, out);
}

// round 17
// speedup vs baseline: 1.0365x; 1.0232x over previous
#include <cuda_runtime.h>
#include <cuda_fp16.h>
#include <math.h>
#include <cstdint>

#define BB 4
#define TT 1024
#define DD 1024
#define HH 16
#define HSS 64

// Scratch (no cudaMalloc allowed)
__device__ __align__(16) __half g_xh[BB*TT*DD];            // x in fp16
__device__ __align__(16) unsigned g_wp[3*HH*512*HSS];      // W q/k/v paired: [which][h][kp][hs]
__device__ __align__(16) unsigned g_wop[512*DD];           // Wo paired: [kp][n]
__device__ __align__(16) __half g_q[BB*HH*TT*HSS];         // pre-scaled by 0.125*log2e
__device__ __align__(16) __half g_k[BB*HH*TT*HSS];
__device__ __align__(16) __half g_v[BB*HH*TT*HSS];
__device__ __align__(16) __half g_att[BB*TT*DD];

// ---------------------------------------------------------------------------
// helpers
// ---------------------------------------------------------------------------
__device__ __forceinline__ void mma16h(float* d, const unsigned* a, const unsigned* b) {
    asm volatile(
        "mma.sync.aligned.m16n8k16.row.col.f32.f16.f16.f32 "
        "{%0,%1,%2,%3}, {%4,%5,%6,%7}, {%8,%9}, {%0,%1,%2,%3};"
        : "+f"(d[0]), "+f"(d[1]), "+f"(d[2]), "+f"(d[3])
        : "r"(a[0]), "r"(a[1]), "r"(a[2]), "r"(a[3]),
          "r"(b[0]), "r"(b[1]));
}

__device__ __forceinline__ void ldsm4(unsigned& r0, unsigned& r1,
                                      unsigned& r2, unsigned& r3, uint32_t addr) {
    asm volatile("ldmatrix.sync.aligned.m8n8.x4.shared.b16 {%0,%1,%2,%3}, [%4];"
                 : "=r"(r0), "=r"(r1), "=r"(r2), "=r"(r3) : "r"(addr));
}

__device__ __forceinline__ unsigned packh2(float a, float b) {
    __half2 h = __floats2half2_rn(a, b);
    return *reinterpret_cast<unsigned*>(&h);
}

__device__ __forceinline__ uint32_t smem_u32(const void* p) {
    uint32_t a;
    asm("{ .reg .u64 t; cvta.to.shared.u64 t, %1; cvt.u32.u64 %0, t; }"
        : "=r"(a) : "l"(p));
    return a;
}

__device__ __forceinline__ void cp16(uint32_t s, const void* g) {
    asm volatile("cp.async.cg.shared.global [%0], [%1], 16;"
                 :: "r"(s), "l"(g) : "memory");
}
#define CP_COMMIT() asm volatile("cp.async.commit_group;" ::: "memory")
#define CP_WAIT1()  asm volatile("cp.async.wait_group 1;" ::: "memory")
#define CP_WAIT0()  asm volatile("cp.async.wait_group 0;" ::: "memory")

// 0.125 (HS^-0.5) * log2(e): folded into Q so softmax runs in exp2 domain.
#define QSCALE 0.180336880f

// ---------------------------------------------------------------------------
// Convert/pack kernel (vectorized; grid 1184 for DRAM MLP)
// ---------------------------------------------------------------------------
__global__ void conv_kernel(const float* __restrict__ x,
                            const float* __restrict__ Wq,
                            const float* __restrict__ Wk,
                            const float* __restrict__ Wv,
                            const float* __restrict__ Wo)
{
    const int stride = gridDim.x * blockDim.x;
    const int tid0 = blockIdx.x * blockDim.x + threadIdx.x;

    const int XN8 = (BB * TT * DD) / 8;
    for (int i = tid0; i < XN8; i += stride) {
        float4 v0 = reinterpret_cast<const float4*>(x)[2 * i];
        float4 v1 = reinterpret_cast<const float4*>(x)[2 * i + 1];
        uint4 o;
        o.x = packh2(v0.x, v0.y);
        o.y = packh2(v0.z, v0.w);
        o.z = packh2(v1.x, v1.y);
        o.w = packh2(v1.z, v1.w);
        reinterpret_cast<uint4*>(g_xh)[i] = o;
    }

    const int WP4 = (3 * HH * 512 * HSS) / 4;
    for (int i = tid0; i < WP4; i += stride) {
        int w0 = i * 4;
        int hs = w0 & 63;
        int kp = (w0 >> 6) & 511;
        int h  = (w0 >> 15) & 15;
        int which = w0 >> 19;
        const float* W = (which == 0 ? Wq : which == 1 ? Wk : Wv);
        const float* s0 = W + ((size_t)h * DD + 2 * kp) * HSS + hs;
        float4 a = *reinterpret_cast<const float4*>(s0);
        float4 b = *reinterpret_cast<const float4*>(s0 + HSS);
        uint4 o;
        o.x = packh2(a.x, b.x); o.y = packh2(a.y, b.y);
        o.z = packh2(a.z, b.z); o.w = packh2(a.w, b.w);
        reinterpret_cast<uint4*>(g_wp)[i] = o;
    }

    const int WO4 = (512 * DD) / 4;
    for (int i = tid0; i < WO4; i += stride) {
        int w0 = i * 4;
        int n  = w0 & 1023;
        int kp = w0 >> 10;
        const float* s0 = Wo + (size_t)(2 * kp) * DD + n;
        float4 a = *reinterpret_cast<const float4*>(s0);
        float4 b = *reinterpret_cast<const float4*>(s0 + DD);
        uint4 o;
        o.x = packh2(a.x, b.x); o.y = packh2(a.y, b.y);
        o.z = packh2(a.z, b.z); o.w = packh2(a.w, b.w);
        reinterpret_cast<uint4*>(g_wop)[i] = o;
    }
}

// ---------------------------------------------------------------------------
// fp16 GEMM: block 128x128, 8 warps = 2(m) x 4(n), warp 64x32, BK=64.
// Aw[row 128][kp 32 + pad4]  -> ldmatrix.x4 for A fragments
// Bw[kp 32][n 128 + pad8]    -> scalar frags (packed k-pairs)
// 3-stage cp.async pipeline, 16 k-chunks.
// ---------------------------------------------------------------------------
#define AW_STRIDE 36
#define BW_STRIDE 136
#define AW_WORDS  (128 * AW_STRIDE)     // 4608
#define BW_WORDS  (32 * BW_STRIDE)      // 4352
#define NSTAGE 3
#define NCHUNK 16
#define PIPE_SMEM ((AW_WORDS + BW_WORDS) * NSTAGE * 4)   // 107520 bytes

__device__ __forceinline__ uint32_t a_lane_off(int lane) {
    int r = (lane & 7) + ((lane >> 3) & 1) * 8;
    int c = (lane & 16) ? 4 : 0;
    return (uint32_t)(r * AW_STRIDE + c) * 4;
}

__device__ __forceinline__ void gemm_mma_chunk(
    uint32_t aw_addr0, const unsigned* __restrict__ Bw,
    float acc[4][4][4], int wn, int lq, int lr)
{
#pragma unroll
    for (int kc = 0; kc < 4; kc++) {
        const int kb = kc * 8 + lr;
        unsigned a[4][4];
#pragma unroll
        for (int mf = 0; mf < 4; mf++)
            ldsm4(a[mf][0], a[mf][1], a[mf][2], a[mf][3],
                  aw_addr0 + (uint32_t)(mf * 16 * AW_STRIDE + kc * 8) * 4);
        unsigned b[4][2];
#pragma unroll
        for (int nf = 0; nf < 4; nf++) {
            int nc = wn * 32 + nf * 8 + lq;
            b[nf][0] = Bw[kb * BW_STRIDE + nc];
            b[nf][1] = Bw[(kb + 4) * BW_STRIDE + nc];
        }
#pragma unroll
        for (int mf = 0; mf < 4; mf++)
#pragma unroll
            for (int nf = 0; nf < 4; nf++)
                mma16h(acc[mf][nf], a[mf], b[nf]);
    }
}

// ---------------------------------------------------------------------------
// QKV: logical GEMM [4096 x 3072 x 1024]. grid (24, 32): x = nt (fast), y = mt.
// Q outputs are pre-scaled by QSCALE (softmax scale folded in).
// ---------------------------------------------------------------------------
__device__ __forceinline__ void qkv_issue(
    uint32_t a_s, uint32_t b_s, int mt, const unsigned* Wp, int h0, int k0, int tid)
{
#pragma unroll
    for (int i = 0; i < 4; i++) {
        int u = tid + i * 256;
        int row = u >> 3;
        int q4  = u & 7;
        cp16(a_s + (row * AW_STRIDE + q4 * 4) * 4,
             &g_xh[(size_t)(mt * 128 + row) * DD + k0 + q4 * 8]);
    }
#pragma unroll
    for (int i = 0; i < 4; i++) {
        int u = tid + i * 256;
        int kp = u >> 5;
        int n  = (u & 31) * 4;
        int h  = h0 + (n >> 6);
        int hs = n & 63;
        cp16(b_s + (kp * BW_STRIDE + n) * 4,
             &Wp[((size_t)h * 512 + (k0 >> 1) + kp) * HSS + hs]);
    }
}

__global__ __launch_bounds__(256, 2) void qkv_kernel()
{
    extern __shared__ unsigned dsm[];
    unsigned* AwB = dsm;
    unsigned* BwB = dsm + NSTAGE * AW_WORDS;
    const uint32_t a_base = smem_u32(AwB);
    const uint32_t b_base = smem_u32(BwB);

    const int nt = blockIdx.x;           // 0..23
    const int mt = blockIdx.y;           // 0..31
    const int which = nt >> 3;
    const int h0 = (nt & 7) * 2;

    __half* dst = (which == 0 ? g_q : which == 1 ? g_k : g_v);
    const unsigned* Wp = g_wp + (size_t)which * HH * 512 * HSS;
    const float oscale = (which == 0) ? QSCALE : 1.0f;

    const int tid  = threadIdx.x;
    const int lane = tid & 31;
    const int warp = tid >> 5;
    const int wm   = warp >> 2;
    const int wn   = warp & 3;
    const int lq   = lane >> 2;
    const int lr   = lane & 3;
    const uint32_t aoff = (uint32_t)(wm * 64 * AW_STRIDE) * 4 + a_lane_off(lane);

    float acc[4][4][4];
#pragma unroll
    for (int mf = 0; mf < 4; mf++)
#pragma unroll
        for (int nf = 0; nf < 4; nf++)
#pragma unroll
            for (int j = 0; j < 4; j++) acc[mf][nf][j] = 0.f;

    qkv_issue(a_base, b_base, mt, Wp, h0, 0, tid);
    CP_COMMIT();
    qkv_issue(a_base + AW_WORDS * 4, b_base + BW_WORDS * 4, mt, Wp, h0, 64, tid);
    CP_COMMIT();

    for (int ci = 0; ci < NCHUNK; ci++) {
        if (ci < NCHUNK - 2) CP_WAIT1(); else CP_WAIT0();
        __syncthreads();
        if (ci + 2 < NCHUNK) {
            int s = (ci + 2) % NSTAGE;
            qkv_issue(a_base + s * AW_WORDS * 4, b_base + s * BW_WORDS * 4,
                      mt, Wp, h0, (ci + 2) * 64, tid);
            CP_COMMIT();
        }
        int s = ci % NSTAGE;
        gemm_mma_chunk(a_base + s * AW_WORDS * 4 + aoff,
                       BwB + s * BW_WORDS, acc, wn, lq, lr);
    }

#pragma unroll
    for (int mf = 0; mf < 4; mf++) {
#pragma unroll
        for (int nf = 0; nf < 4; nf++) {
            int row = wm * 64 + mf * 16 + lq;
            int col = wn * 32 + nf * 8 + 2 * lr;
            int h   = h0 + (col >> 6);
            int hs  = col & 63;
#pragma unroll
            for (int half = 0; half < 2; half++) {
                int gr = mt * 128 + row + half * 8;
                int b = gr >> 10, t = gr & 1023;
                __half2* dp = reinterpret_cast<__half2*>(
                    dst + ((size_t)(b * HH + h) * TT + t) * HSS + hs);
                *dp = __floats2half2_rn(acc[mf][nf][half * 2] * oscale,
                                        acc[mf][nf][half * 2 + 1] * oscale);
            }
        }
    }
}

// ---------------------------------------------------------------------------
// Output projection: out[4096,1024] = g_att @ Wo + bo.  grid (32, 8).
// ---------------------------------------------------------------------------
__device__ __forceinline__ void proj_issue(
    uint32_t a_s, uint32_t b_s, int mt, int nt, int k0, int tid)
{
#pragma unroll
    for (int i = 0; i < 4; i++) {
        int u = tid + i * 256;
        int row = u >> 3;
        int q4  = u & 7;
        cp16(a_s + (row * AW_STRIDE + q4 * 4) * 4,
             &g_att[(size_t)(mt * 128 + row) * DD + k0 + q4 * 8]);
    }
#pragma unroll
    for (int i = 0; i < 4; i++) {
        int u = tid + i * 256;
        int kp = u >> 5;
        int n  = (u & 31) * 4;
        cp16(b_s + (kp * BW_STRIDE + n) * 4,
             &g_wop[((size_t)(k0 >> 1) + kp) * DD + nt * 128 + n]);
    }
}

__global__ __launch_bounds__(256, 2) void proj_kernel(
    const float* __restrict__ bo, float* __restrict__ out)
{
    extern __shared__ unsigned dsm[];
    unsigned* AwB = dsm;
    unsigned* BwB = dsm + NSTAGE * AW_WORDS;
    const uint32_t a_base = smem_u32(AwB);
    const uint32_t b_base = smem_u32(BwB);

    const int mt = blockIdx.x;
    const int nt = blockIdx.y;

    const int tid  = threadIdx.x;
    const int lane = tid & 31;
    const int warp = tid >> 5;
    const int wm   = warp >> 2;
    const int wn   = warp & 3;
    const int lq   = lane >> 2;
    const int lr   = lane & 3;
    const uint32_t aoff = (uint32_t)(wm * 64 * AW_STRIDE) * 4 + a_lane_off(lane);

    float acc[4][4][4];
#pragma unroll
    for (int mf = 0; mf < 4; mf++)
#pragma unroll
        for (int nf = 0; nf < 4; nf++)
#pragma unroll
            for (int j = 0; j < 4; j++) acc[mf][nf][j] = 0.f;

    proj_issue(a_base, b_base, mt, nt, 0, tid);
    CP_COMMIT();
    proj_issue(a_base + AW_WORDS * 4, b_base + BW_WORDS * 4, mt, nt, 64, tid);
    CP_COMMIT();

    for (int ci = 0; ci < NCHUNK; ci++) {
        if (ci < NCHUNK - 2) CP_WAIT1(); else CP_WAIT0();
        __syncthreads();
        if (ci + 2 < NCHUNK) {
            int s = (ci + 2) % NSTAGE;
            proj_issue(a_base + s * AW_WORDS * 4, b_base + s * BW_WORDS * 4,
                       mt, nt, (ci + 2) * 64, tid);
            CP_COMMIT();
        }
        int s = ci % NSTAGE;
        gemm_mma_chunk(a_base + s * AW_WORDS * 4 + aoff,
                       BwB + s * BW_WORDS, acc, wn, lq, lr);
    }

#pragma unroll
    for (int mf = 0; mf < 4; mf++) {
#pragma unroll
        for (int nf = 0; nf < 4; nf++) {
            int row = wm * 64 + mf * 16 + lq;
            int col = nt * 128 + wn * 32 + nf * 8 + 2 * lr;
            float b0 = bo[col], b1 = bo[col + 1];
            float* C0 = out + (size_t)(mt * 128 + row) * DD + col;
            float* C1 = out + (size_t)(mt * 128 + row + 8) * DD + col;
            *reinterpret_cast<float2*>(C0) =
                make_float2(acc[mf][nf][0] + b0, acc[mf][nf][1] + b1);
            *reinterpret_cast<float2*>(C1) =
                make_float2(acc[mf][nf][2] + b0, acc[mf][nf][3] + b1);
        }
    }
}

// ---------------------------------------------------------------------------
// Causal flash attention, fp16 m16n8k16. Block = 256 threads (8 warps),
// q-tile 128; 1D grid of 512 ordered heavy-first globally:
// it = 7 - (i >> 6), bh = i & 63.
// Q pre-scaled by 0.125*log2e -> softmax in exp2 domain.
// cp.async double-buffered K + raw-V prefetch; V perm is smem->smem.
// ---------------------------------------------------------------------------
#define ATQ_WORDS (128 * 36)            // 4608
#define ATK_WORDS (64 * 36)             // 2304
#define ATV_WORDS (32 * 72)             // 2304
#define ATTN_SMEM ((ATQ_WORDS + 2 * ATK_WORDS + 2 * ATK_WORDS + ATV_WORDS) * 4) // 64512

__global__ __launch_bounds__(256) void attn_kernel()
{
    extern __shared__ unsigned sdyn[];
    unsigned* Qs  = sdyn;
    unsigned* KsB = sdyn + ATQ_WORDS;                    // 2 buffers
    unsigned* VrB = sdyn + ATQ_WORDS + 2 * ATK_WORDS;    // 2 buffers (raw V)
    unsigned* Vs  = sdyn + ATQ_WORDS + 4 * ATK_WORDS;    // single (perm'd)

    const int idx = blockIdx.x;                  // 0..511
    const int it  = (TT / 128 - 1) - (idx >> 6); // heavy tiles first, globally
    const int bh  = idx & 63;
    const int b = bh >> 4, h = bh & 15;

    const __half* Q  = g_q + (size_t)bh * TT * HSS + (size_t)it * 128 * HSS;
    const __half* Kg = g_k + (size_t)bh * TT * HSS;
    const __half* Vg = g_v + (size_t)bh * TT * HSS;

    const int tid  = threadIdx.x;
    const int lane = tid & 31;
    const int warp = tid >> 5;
    const int lq   = lane >> 2;
    const int lr   = lane & 3;
    const int mrow = warp * 16 + lq;

    const uint32_t ks_base = smem_u32(KsB);
    const uint32_t vr_base = smem_u32(VrB);
    const uint32_t q_addr0 = smem_u32(Qs) + (uint32_t)(warp * 16 * 36) * 4 + a_lane_off(lane);
    const int krow_l = (lane & 7) + ((lane >> 4) & 1) * 8;
    const int kcol_l = ((lane >> 3) & 1) * 4;

    const int ld_row0 = tid >> 3;          // 0..31
    const int ld_u    = tid & 7;           // 0..7

    // Load Q tile: 128 rows x 8 uint4 (once per block)
#pragma unroll
    for (int i = 0; i < 4; i++) {
        int l = tid + i * 256;
        int row = l >> 3;
        int u   = l & 7;
        uint4 v = *reinterpret_cast<const uint4*>(&Q[(size_t)row * HSS + u * 8]);
        *reinterpret_cast<uint4*>(&Qs[row * 36 + u * 4]) = v;
    }

    const int ntiles = 2 * it + 2;

    // prologue: issue tile 0 into buffer 0
    {
        uint32_t kd = ks_base;
        uint32_t vd = vr_base;
#pragma unroll
        for (int i = 0; i < 2; i++) {
            int row = ld_row0 + i * 32;
            cp16(kd + (uint32_t)(row * 36 + ld_u * 4) * 4, &Kg[(size_t)row * HSS + ld_u * 8]);
            cp16(vd + (uint32_t)(row * 36 + ld_u * 4) * 4, &Vg[(size_t)row * HSS + ld_u * 8]);
        }
        CP_COMMIT();
    }

    float m0 = -1e30f, m1 = -1e30f, l0 = 0.f, l1 = 0.f;
    float o[8][4];
#pragma unroll
    for (int j = 0; j < 8; j++)
#pragma unroll
        for (int c = 0; c < 4; c++) o[j][c] = 0.f;

    for (int jt = 0; jt < ntiles; jt++) {
        const int buf  = jt & 1;
        if (jt + 1 < ntiles) {
            const __half* Kn = Kg + (size_t)(jt + 1) * 64 * HSS;
            const __half* Vn = Vg + (size_t)(jt + 1) * 64 * HSS;
            uint32_t kd = ks_base + (uint32_t)((1 - buf) * ATK_WORDS) * 4;
            uint32_t vd = vr_base + (uint32_t)((1 - buf) * ATK_WORDS) * 4;
#pragma unroll
            for (int i = 0; i < 2; i++) {
                int row = ld_row0 + i * 32;
                cp16(kd + (uint32_t)(row * 36 + ld_u * 4) * 4, &Kn[(size_t)row * HSS + ld_u * 8]);
                cp16(vd + (uint32_t)(row * 36 + ld_u * 4) * 4, &Vn[(size_t)row * HSS + ld_u * 8]);
            }
            CP_COMMIT();
            CP_WAIT1();
        } else {
            CP_WAIT0();
        }
        __syncthreads();   // current K/Vr visible; all warps done with prior Vs

        // perm raw V -> Vs (smem -> smem)
        {
            const unsigned* Vr = VrB + buf * ATK_WORDS;
            int kp = tid >> 3;
            int no = tid & 7;
            uint4 r0 = *reinterpret_cast<const uint4*>(&Vr[(2 * kp) * 36 + no * 4]);
            uint4 r1 = *reinterpret_cast<const uint4*>(&Vr[(2 * kp + 1) * 36 + no * 4]);
            uint4 w0, w1;
            w0.x = __byte_perm(r0.x, r1.x, 0x5410);
            w0.y = __byte_perm(r0.x, r1.x, 0x7632);
            w0.z = __byte_perm(r0.y, r1.y, 0x5410);
            w0.w = __byte_perm(r0.y, r1.y, 0x7632);
            w1.x = __byte_perm(r0.z, r1.z, 0x5410);
            w1.y = __byte_perm(r0.z, r1.z, 0x7632);
            w1.z = __byte_perm(r0.w, r1.w, 0x5410);
            w1.w = __byte_perm(r0.w, r1.w, 0x7632);
            *reinterpret_cast<uint4*>(&Vs[kp * 72 + no * 8])     = w0;
            *reinterpret_cast<uint4*>(&Vs[kp * 72 + no * 8 + 4]) = w1;
        }
        __syncthreads();   // Vs ready

        if (jt == 2 * it + 1 && warp < 4) continue;

        const uint32_t k_addr0 = ks_base + (uint32_t)(buf * ATK_WORDS) * 4
                               + (uint32_t)(krow_l * 36 + kcol_l) * 4;

        // ---- S = Q K^T  (already scaled: log2-domain logits)
        float s[8][4];
#pragma unroll
        for (int j = 0; j < 8; j++)
#pragma unroll
            for (int c = 0; c < 4; c++) s[j][c] = 0.f;

#pragma unroll
        for (int c = 0; c < 4; c++) {
            unsigned a[4];
            ldsm4(a[0], a[1], a[2], a[3], q_addr0 + (uint32_t)(c * 8) * 4);
#pragma unroll
            for (int jp = 0; jp < 4; jp++) {
                unsigned b0, b1, b2, b3;
                ldsm4(b0, b1, b2, b3,
                      k_addr0 + (uint32_t)(jp * 16 * 36 + c * 8) * 4);
                unsigned bb0[2] = {b0, b1};
                unsigned bb1[2] = {b2, b3};
                mma16h(s[2 * jp],     a, bb0);
                mma16h(s[2 * jp + 1], a, bb1);
            }
        }

        if (jt >= 2 * it) {
            int gr0 = it * 128 + mrow, gr1 = gr0 + 8;
            int gc_base = jt * 64;
#pragma unroll
            for (int j = 0; j < 8; j++) {
                int c0 = gc_base + j * 8 + 2 * lr, c1 = c0 + 1;
                if (c0 > gr0) s[j][0] = -1e30f;
                if (c1 > gr0) s[j][1] = -1e30f;
                if (c0 > gr1) s[j][2] = -1e30f;
                if (c1 > gr1) s[j][3] = -1e30f;
            }
        }

        // ---- online softmax (exp2 domain)
        float mx0 = -1e30f, mx1 = -1e30f;
#pragma unroll
        for (int j = 0; j < 8; j++) {
            mx0 = fmaxf(mx0, fmaxf(s[j][0], s[j][1]));
            mx1 = fmaxf(mx1, fmaxf(s[j][2], s[j][3]));
        }
        mx0 = fmaxf(mx0, __shfl_xor_sync(0xffffffffu, mx0, 1));
        mx0 = fmaxf(mx0, __shfl_xor_sync(0xffffffffu, mx0, 2));
        mx1 = fmaxf(mx1, __shfl_xor_sync(0xffffffffu, mx1, 1));
        mx1 = fmaxf(mx1, __shfl_xor_sync(0xffffffffu, mx1, 2));

        float mn0 = fmaxf(m0, mx0), mn1 = fmaxf(m1, mx1);
        float f0 = exp2f(m0 - mn0), f1 = exp2f(m1 - mn1);

        float rs0 = 0.f, rs1 = 0.f;
#pragma unroll
        for (int j = 0; j < 8; j++) {
            s[j][0] = exp2f(s[j][0] - mn0);
            s[j][1] = exp2f(s[j][1] - mn0);
            s[j][2] = exp2f(s[j][2] - mn1);
            s[j][3] = exp2f(s[j][3] - mn1);
            rs0 += s[j][0] + s[j][1];
            rs1 += s[j][2] + s[j][3];
        }
        rs0 += __shfl_xor_sync(0xffffffffu, rs0, 1);
        rs0 += __shfl_xor_sync(0xffffffffu, rs0, 2);
        rs1 += __shfl_xor_sync(0xffffffffu, rs1, 1);
        rs1 += __shfl_xor_sync(0xffffffffu, rs1, 2);

        l0 = l0 * f0 + rs0;
        l1 = l1 * f1 + rs1;
        m0 = mn0; m1 = mn1;
#pragma unroll
        for (int j = 0; j < 8; j++) {
            o[j][0] *= f0; o[j][1] *= f0;
            o[j][2] *= f1; o[j][3] *= f1;
        }

        // ---- O += P V  (P packed from registers)
#pragma unroll
        for (int c = 0; c < 4; c++) {
            unsigned a[4];
            a[0] = packh2(s[2 * c][0],     s[2 * c][1]);
            a[1] = packh2(s[2 * c][2],     s[2 * c][3]);
            a[2] = packh2(s[2 * c + 1][0], s[2 * c + 1][1]);
            a[3] = packh2(s[2 * c + 1][2], s[2 * c + 1][3]);
            const int kb = c * 8 + lr;
#pragma unroll
            for (int j = 0; j < 8; j++) {
                unsigned bb[2];
                bb[0] = Vs[kb * 72 + j * 8 + lq];
                bb[1] = Vs[(kb + 4) * 72 + j * 8 + lq];
                mma16h(o[j], a, bb);
            }
        }
    }

    float inv0 = 1.f / l0, inv1 = 1.f / l1;
    size_t row0 = (size_t)b * TT + (size_t)it * 128 + mrow;
    size_t row1 = row0 + 8;
#pragma unroll
    for (int j = 0; j < 8; j++) {
        int cb = h * HSS + j * 8 + 2 * lr;
        *reinterpret_cast<__half2*>(&g_att[row0 * DD + cb]) =
            __floats2half2_rn(o[j][0] * inv0, o[j][1] * inv0);
        *reinterpret_cast<__half2*>(&g_att[row1 * DD + cb]) =
            __floats2half2_rn(o[j][2] * inv1, o[j][3] * inv1);
    }
}

extern "C" void kernel_launch(void* const* d_in, const int* in_sizes, int n_in,
                              void* d_out, int out_size)
{
    const float* x  = (const float*)d_in[0];
    const float* Wq = (const float*)d_in[1];
    const float* Wk = (const float*)d_in[2];
    const float* Wv = (const float*)d_in[3];
    const float* Wo = (const float*)d_in[4];
    const float* bo = (const float*)d_in[5];
    float* out = (float*)d_out;

    cudaFuncSetAttribute(qkv_kernel,
                         cudaFuncAttributeMaxDynamicSharedMemorySize, PIPE_SMEM);
    cudaFuncSetAttribute(proj_kernel,
                         cudaFuncAttributeMaxDynamicSharedMemorySize, PIPE_SMEM);
    cudaFuncSetAttribute(attn_kernel,
                         cudaFuncAttributeMaxDynamicSharedMemorySize, ATTN_SMEM);

    conv_kernel<<<1184, 256>>>(x, Wq, Wk, Wv, Wo);

    dim3 g1(24, (BB * TT) / 128);
    qkv_kernel<<<g1, 256, PIPE_SMEM>>>();

    attn_kernel<<<(TT / 128) * BB * HH, 256, ATTN_SMEM>>>();

    dim3 g3((BB * TT) / 128, DD / 128);
    proj_kernel<<<g3, 256, PIPE_SMEM>>>(bo, out);
}